// round 11
// baseline (speedup 1.0000x reference)
#include <cuda_runtime.h>
#include <cstdint>

typedef unsigned long long ull;

#define BATCH 1024
#define TLEN  200
#define DDIM  128
#define HDIM  128
#define NXC   384
#define MROWS (BATCH * TLEN)
#define GROUPS 256

// compact x-projection (sorted-row-major) + perm/offsets
__device__ float g_xproj[(size_t)MROWS * NXC];
__device__ int   g_perm[BATCH];
__device__ int   g_coff[BATCH + 1];
// packed tf32 hi/lo weight fragments: [24 mt][16 ks][32 lane][hi uint4, lo uint4]
__device__ uint4 g_wpack[24 * 16 * 32 * 2];

// ---------- packed f32x2 helpers ----------
__device__ __forceinline__ ull dup2(float v) {
    ull r; asm("mov.b64 %0,{%1,%1};" : "=l"(r) : "f"(v)); return r;
}
__device__ __forceinline__ ull pack2(float x, float y) {
    ull r; asm("mov.b64 %0,{%1,%2};" : "=l"(r) : "f"(x), "f"(y)); return r;
}
__device__ __forceinline__ float2 unpack2(ull v) {
    float2 f; asm("mov.b64 {%0,%1},%2;" : "=f"(f.x), "=f"(f.y) : "l"(v)); return f;
}
__device__ __forceinline__ void ffma2(ull &d, ull a, ull b) {
    asm("fma.rn.f32x2 %0,%1,%2,%0;" : "+l"(d) : "l"(a), "l"(b));
}
__device__ __forceinline__ ull addf2(ull a, ull b) {
    ull r; asm("add.rn.f32x2 %0,%1,%2;" : "=l"(r) : "l"(a), "l"(b)); return r;
}
__device__ __forceinline__ float tanhap(float x) {
    float r; asm("tanh.approx.f32 %0,%1;" : "=f"(r) : "f"(x)); return r;
}
__device__ __forceinline__ float sigap(float x) {
    return fmaf(tanhap(0.5f * x), 0.5f, 0.5f);
}
__device__ __forceinline__ uint32_t tf32rna(float x) {
    uint32_t r; asm("cvt.rna.tf32.f32 %0, %1;" : "=r"(r) : "f"(x)); return r;
}
// mma.sync m16n8k8 tf32: D += A*B (acc in-place)
__device__ __forceinline__ void mma8(float* d, uint32_t a0, uint32_t a1, uint32_t a2, uint32_t a3,
                                     uint32_t b0, uint32_t b1) {
    asm volatile("mma.sync.aligned.m16n8k8.row.col.f32.tf32.tf32.f32 "
        "{%0,%1,%2,%3}, {%4,%5,%6,%7}, {%8,%9}, {%0,%1,%2,%3};"
        : "+f"(d[0]), "+f"(d[1]), "+f"(d[2]), "+f"(d[3])
        : "r"(a0), "r"(a1), "r"(a2), "r"(a3), "r"(b0), "r"(b1));
}

// =====================================================================
// Kernel 0: counting sort rows by seq_len DESC -> g_perm; exclusive
// prefix sum of sorted lengths -> g_coff.
// =====================================================================
__global__ void __launch_bounds__(1024) dien_sort_kernel(const int* __restrict__ seq)
{
    __shared__ int s[1024];
    __shared__ int sperm[1024];
    __shared__ int cnt[256];
    __shared__ int cur[256];
    __shared__ int buf[1024];
    const int tid = threadIdx.x;

    s[tid] = seq[tid];
    if (tid < 256) { cnt[tid] = 0; cur[tid] = 0; }
    __syncthreads();
    atomicAdd(&cnt[s[tid] & 255], 1);
    __syncthreads();
    if (tid < 256) buf[tid] = cnt[tid];
    __syncthreads();
    for (int off = 1; off < 256; off <<= 1) {
        int v = 0;
        if (tid < 256) { v = buf[tid]; if (tid + off < 256) v += buf[tid + off]; }
        __syncthreads();
        if (tid < 256) buf[tid] = v;
        __syncthreads();
    }
    {
        int v = s[tid] & 255;
        int start = buf[v] - cnt[v];
        int rank = atomicAdd(&cur[v], 1);
        sperm[start + rank] = tid;
    }
    __syncthreads();
    g_perm[tid] = sperm[tid];
    int sl = s[sperm[tid]];
    buf[tid] = sl;
    __syncthreads();
    for (int off = 1; off < 1024; off <<= 1) {
        int v = buf[tid] + ((tid >= off) ? buf[tid - off] : 0);
        __syncthreads();
        buf[tid] = v;
        __syncthreads();
    }
    g_coff[tid] = buf[tid] - sl;
    if (tid == 1023) g_coff[1024] = buf[1023];
}

// =====================================================================
// Kernel 0b: pack weight fragments (hi/lo tf32 split).
// Fragment (mt, ks, lane): A[m=gid][k=tig..] with A[m][k] = W[k][mt*16+m].
// =====================================================================
__global__ void __launch_bounds__(256) dien_prep_kernel(
    const float* __restrict__ Wg, const float* __restrict__ Wc)
{
    int idx = blockIdx.x * 256 + threadIdx.x;   // < 24*16*32 = 12288
    if (idx >= 12288) return;
    int l = idx & 31, ks = (idx >> 5) & 15, mt = idx >> 9;
    int tig = l & 3, gid = l >> 2;
    int c0 = mt * 16 + gid, c1 = c0 + 8;
    int k0 = ks * 8 + tig, k1 = k0 + 4;

    float w[4];
    // a0=(k0,c0) a1=(k0,c1) a2=(k1,c0) a3=(k1,c1)
    w[0] = (c0 < 256) ? Wg[k0 * 256 + c0] : Wc[k0 * 128 + c0 - 256];
    w[1] = (c1 < 256) ? Wg[k0 * 256 + c1] : Wc[k0 * 128 + c1 - 256];
    w[2] = (c0 < 256) ? Wg[k1 * 256 + c0] : Wc[k1 * 128 + c0 - 256];
    w[3] = (c1 < 256) ? Wg[k1 * 256 + c1] : Wc[k1 * 128 + c1 - 256];

    uint4 hi, lo;
    uint32_t* hp = &hi.x; uint32_t* lp = &lo.x;
    #pragma unroll
    for (int i = 0; i < 4; i++) {
        uint32_t h = tf32rna(w[i]);
        hp[i] = h;
        lp[i] = tf32rna(w[i] - __uint_as_float(h));
    }
    size_t base = ((size_t)(mt * 16 + ks) * 32 + l) * 2;
    g_wpack[base] = hi;
    g_wpack[base + 1] = lo;
}

// =====================================================================
// Phase 1: split-tf32 mma.sync xproj. CTA = 128 compact rows x 384 cols.
// 256 thr / 8 warps; warp = 16 cols (m-tile) x 128 rows; 3 rounds.
// B (x rows) fragment-packed hi/lo in smem; A (weights) from g_wpack.
// =====================================================================
__global__ void __launch_bounds__(256, 1) dien_xproj_mma(
    const float* __restrict__ X,
    const float* __restrict__ bg, const float* __restrict__ bc)
{
    extern __shared__ char smraw[];
    float4* Xp4 = (float4*)smraw;                    // [128 row][65] 16B recs = 133120 B
    int* scoff  = (int*)(smraw + 133120);            // 1025
    int* srcrow = scoff + 1025;                      // 128

    const int tid  = threadIdx.x;
    const int lane = tid & 31;
    const int w    = tid >> 5;
    const int r0   = blockIdx.x * 128;

    const int total = g_coff[1024];
    if (r0 >= total) return;

    for (int i = tid; i < 1025; i += 256) scoff[i] = g_coff[i];
    __syncthreads();
    if (tid < 128) {
        int vr = r0 + tid;
        int sr = -1;
        if (vr < total) {
            int lo = 0, hi = 1024;
            while (hi - lo > 1) { int mid = (lo + hi) >> 1; if (scoff[mid] <= vr) lo = mid; else hi = mid; }
            sr = g_perm[lo] * TLEN + (vr - scoff[lo]);
        }
        srcrow[tid] = sr;
    }
    __syncthreads();

    // ---- gather + hi/lo split into fragment-packed layout ----
    // record (row, ks, tig) = {hi(k), hi(k+4), lo(k), lo(k+4)}, k = ks*8+tig
    {
        const float4* X4 = (const float4*)X;
        float* Xf = (float*)Xp4;
        for (int idx = tid; idx < 4096; idx += 256) {
            int row = idx >> 5, k4 = idx & 31;
            int sr = srcrow[row];
            float4 v = make_float4(0.f, 0.f, 0.f, 0.f);
            if (sr >= 0) v = X4[(size_t)sr * 32 + k4];
            #pragma unroll
            for (int j = 0; j < 4; j++) {
                int k = k4 * 4 + j;
                float x = (j == 0) ? v.x : (j == 1) ? v.y : (j == 2) ? v.z : v.w;
                uint32_t hb = tf32rna(x);
                uint32_t lb = tf32rna(x - __uint_as_float(hb));
                int ks = k >> 3, within = k & 7;
                int tg = within & 3, half = within >> 2;
                int base = (row * 65 + ks * 4 + tg) * 4;
                Xf[base + half]     = __uint_as_float(hb);
                Xf[base + 2 + half] = __uint_as_float(lb);
            }
        }
    }
    __syncthreads();

    const int tig = lane & 3, gid = lane >> 2;

    for (int round = 0; round < 3; round++) {
        const int mt = round * 8 + w;
        const uint4* wp = g_wpack + ((size_t)(mt * 16) * 32 + lane) * 2;

        float acc[16][4];
        #pragma unroll
        for (int nf = 0; nf < 16; nf++)
            #pragma unroll
            for (int i = 0; i < 4; i++) acc[nf][i] = 0.f;

        #pragma unroll 2
        for (int ks = 0; ks < 16; ks++) {
            uint4 ah = wp[(size_t)ks * 64];
            uint4 al = wp[(size_t)ks * 64 + 1];
            #pragma unroll
            for (int nf = 0; nf < 16; nf++) {
                float4 b = Xp4[(nf * 8 + gid) * 65 + ks * 4 + tig];
                uint32_t bh0 = __float_as_uint(b.x), bh1 = __float_as_uint(b.y);
                uint32_t bl0 = __float_as_uint(b.z), bl1 = __float_as_uint(b.w);
                mma8(acc[nf], ah.x, ah.y, ah.z, ah.w, bh0, bh1);
                mma8(acc[nf], ah.x, ah.y, ah.z, ah.w, bl0, bl1);
                mma8(acc[nf], al.x, al.y, al.z, al.w, bh0, bh1);
            }
        }

        // ---- epilogue: D[m=outcol][n=outrow]; add bias; guarded stores ----
        int col0 = mt * 16 + gid, col1 = col0 + 8;
        float bias0 = (col0 < 256) ? bg[col0] : bc[col0 - 256];
        float bias1 = (col1 < 256) ? bg[col1] : bc[col1 - 256];
        #pragma unroll
        for (int nf = 0; nf < 16; nf++) {
            int row0 = nf * 8 + 2 * tig, row1 = row0 + 1;
            int vr0 = r0 + row0, vr1 = r0 + row1;
            if (vr0 < total) {
                g_xproj[(size_t)vr0 * NXC + col0] = acc[nf][0] + bias0;
                g_xproj[(size_t)vr0 * NXC + col1] = acc[nf][2] + bias1;
            }
            if (vr1 < total) {
                g_xproj[(size_t)vr1 * NXC + col0] = acc[nf][1] + bias0;
                g_xproj[(size_t)vr1 * NXC + col1] = acc[nf][3] + bias1;
            }
        }
    }
}

// =====================================================================
// Phase 2 (unchanged R8): GRU on sorted 4-row groups. 256 CTAs x 512 thr.
// =====================================================================
__global__ void __launch_bounds__(512, 1) dien_gru_kernel(
    const float* __restrict__ Wg, const float* __restrict__ Wc,
    const int* __restrict__ seqlen, float* __restrict__ out)
{
    extern __shared__ char smraw[];
    float* whc = (float*)smraw;                 // [128 k][128 col]   65536 B
    ull*   hp  = (ull*)(smraw + 65536);         // [2 pair][128 k]     2048 B
    ull*   rhp = hp + 256;                      // [2 pair][128 k]     2048 B
    ull*   red = rhp + 256;                     // 4096 ull           32768 B

    const int tid = threadIdx.x;
    const int jc  = tid & 127;
    const int q   = tid >> 7;            // 0..3, k-split 32
    const int k0  = q * 32;

    for (int i = tid; i < 128 * 128; i += 512) whc[i] = Wc[128 * 128 + i];

    float wgr[32], wgu[32];
    #pragma unroll
    for (int i = 0; i < 32; i++) {
        wgr[i] = Wg[(size_t)(128 + k0 + i) * 256 + jc];
        wgu[i] = Wg[(size_t)(128 + k0 + i) * 256 + jc + 128];
    }

    const int g  = blockIdx.x;
    const int rA0 = g_perm[4 * g];
    const int maxseq = seqlen[rA0];

    const int posA = 4 * g + 2 * (q & 1);
    const int posB = posA + 1;
    const int rowA = g_perm[(q < 2) ? posA : 4 * g];
    const int rowB = g_perm[(q < 2) ? posB : 4 * g];
    const int cofA = g_coff[(q < 2) ? posA : 4 * g];
    const int cofB = g_coff[(q < 2) ? posB : 4 * g];
    const int sqa = seqlen[rowA];
    const int sqb = seqlen[rowB];

    if (tid < 256) hp[tid] = 0ull;
    __syncthreads();

    const float* xa = g_xproj + (size_t)cofA * NXC + jc;
    const float* xb = g_xproj + (size_t)cofB * NXC + jc;
    float* oa = out + (size_t)rowA * TLEN * HDIM + jc;
    float* ob = out + (size_t)rowB * TLEN * HDIM + jc;

    const ulonglong2* h2 = (const ulonglong2*)hp  + (k0 >> 1);
    const ulonglong2* r2 = (const ulonglong2*)rhp + (k0 >> 1);
    const float* wcp = whc + k0 * 128 + jc;

    for (int t = 0; t < maxseq; t++) {
        float xra = 0.f, xrb = 0.f, xua = 0.f, xub = 0.f, xca = 0.f, xcb = 0.f;
        if (q < 2) {
            const float* p0 = xa + (size_t)t * NXC;
            const float* p1 = xb + (size_t)t * NXC;
            if (t < sqa) { xra = p0[0]; xua = p0[128]; xca = p0[256]; }
            if (t < sqb) { xrb = p1[0]; xub = p1[128]; xcb = p1[256]; }
        }

        ull ar0 = 0, ar1 = 0, au0 = 0, au1 = 0;
        #pragma unroll
        for (int i = 0; i < 16; i++) {
            ulonglong2 a0 = h2[i];
            ulonglong2 a1 = h2[64 + i];
            ull w0 = dup2(wgr[2 * i]), w1 = dup2(wgr[2 * i + 1]);
            ull v0 = dup2(wgu[2 * i]), v1 = dup2(wgu[2 * i + 1]);
            ffma2(ar0, a0.x, w0); ffma2(ar0, a0.y, w1);
            ffma2(ar1, a1.x, w0); ffma2(ar1, a1.y, w1);
            ffma2(au0, a0.x, v0); ffma2(au0, a0.y, v1);
            ffma2(au1, a1.x, v0); ffma2(au1, a1.y, v1);
        }
        {
            ull* st = red + q * 1024 + jc;
            st[0]   = ar0; st[128] = ar1;
            st[512] = au0; st[640] = au1;
        }
        __syncthreads();

        float r_a, r_b, u_a, u_b; float2 Ho;
        if (q < 2) {
            const ull* rd = red + q * 128 + jc;
            ull zr = rd[0], zu = rd[512];
            #pragma unroll
            for (int qq = 1; qq < 4; qq++) {
                zr = addf2(zr, rd[qq * 1024]);
                zu = addf2(zu, rd[qq * 1024 + 512]);
            }
            float2 Zr = unpack2(zr), Zu = unpack2(zu);
            r_a = sigap(Zr.x + xra); r_b = sigap(Zr.y + xrb);
            u_a = sigap(Zu.x + xua); u_b = sigap(Zu.y + xub);
            Ho = unpack2(hp[q * 128 + jc]);
            rhp[q * 128 + jc] = pack2(r_a * Ho.x, r_b * Ho.y);
        }
        __syncthreads();

        ull c0 = 0, c1 = 0;
        #pragma unroll
        for (int i = 0; i < 16; i++) {
            ulonglong2 a0 = r2[i];
            ulonglong2 a1 = r2[64 + i];
            ull w0 = dup2(wcp[(2 * i) * 128]);
            ull w1 = dup2(wcp[(2 * i + 1) * 128]);
            ffma2(c0, a0.x, w0); ffma2(c0, a0.y, w1);
            ffma2(c1, a1.x, w0); ffma2(c1, a1.y, w1);
        }
        {
            ull* st = red + q * 256 + jc;
            st[0] = c0; st[128] = c1;
        }
        __syncthreads();

        if (q < 2) {
            const ull* rd = red + q * 128 + jc;
            ull zc = rd[0];
            #pragma unroll
            for (int qq = 1; qq < 4; qq++) zc = addf2(zc, rd[qq * 256]);
            float2 Zc = unpack2(zc);
            float c_a = tanhap(Zc.x + xca);
            float c_b = tanhap(Zc.y + xcb);
            float hna = fmaf(u_a, Ho.x - c_a, c_a);
            float hnb = fmaf(u_b, Ho.y - c_b, c_b);
            bool va = t < sqa, vb = t < sqb;
            hp[q * 128 + jc] = pack2(va ? hna : Ho.x, vb ? hnb : Ho.y);
            if (va) oa[(size_t)t * HDIM] = hna;
            if (vb) ob[(size_t)t * HDIM] = hnb;
        }
        __syncthreads();
    }
}

// =====================================================================
extern "C" void kernel_launch(void* const* d_in, const int* in_sizes, int n_in,
                              void* d_out, int out_size)
{
    const float* X   = (const float*)d_in[0];
    const int*   seq = (const int*)  d_in[1];
    const float* Wg  = (const float*)d_in[2];
    const float* bg  = (const float*)d_in[3];
    const float* Wc  = (const float*)d_in[4];
    const float* bc  = (const float*)d_in[5];
    float* out = (float*)d_out;
    (void)in_sizes; (void)n_in;

    const int SMEM_MMA = 133120 + 1025 * 4 + 128 * 4 + 256;   // ~137.9 KB
    const int SMEM2 = 65536 + 2048 + 2048 + 32768;            // 102400 B
    cudaFuncSetAttribute(dien_xproj_mma, cudaFuncAttributeMaxDynamicSharedMemorySize, SMEM_MMA);
    cudaFuncSetAttribute(dien_gru_kernel, cudaFuncAttributeMaxDynamicSharedMemorySize, SMEM2);

    cudaMemsetAsync(d_out, 0, (size_t)out_size * sizeof(float));

    dien_sort_kernel<<<1, 1024>>>(seq);
    dien_prep_kernel<<<48, 256>>>(Wg, Wc);
    dien_xproj_mma<<<1600, 256, SMEM_MMA>>>(X, bg, bc);
    dien_gru_kernel<<<GROUPS, 512, SMEM2>>>(Wg, Wc, seq, out);
}

// round 12
// speedup vs baseline: 1.0584x; 1.0584x over previous
#include <cuda_runtime.h>
#include <cstdint>

typedef unsigned long long ull;

#define BATCH 1024
#define TLEN  200
#define DDIM  128
#define HDIM  128
#define NXC   384
#define MROWS (BATCH * TLEN)
#define GROUPS 256

// compact x-projection (sorted-row-major) + perm/offsets
__device__ float g_xproj[(size_t)MROWS * NXC];
__device__ int   g_perm[BATCH];
__device__ int   g_coff[BATCH + 1];
// packed tf32 hi/lo weight fragments: [24 mt][16 ks][32 lane][hi uint4, lo uint4]
__device__ uint4 g_wpack[24 * 16 * 32 * 2];

// ---------- packed f32x2 helpers ----------
__device__ __forceinline__ ull dup2(float v) {
    ull r; asm("mov.b64 %0,{%1,%1};" : "=l"(r) : "f"(v)); return r;
}
__device__ __forceinline__ ull pack2(float x, float y) {
    ull r; asm("mov.b64 %0,{%1,%2};" : "=l"(r) : "f"(x), "f"(y)); return r;
}
__device__ __forceinline__ float2 unpack2(ull v) {
    float2 f; asm("mov.b64 {%0,%1},%2;" : "=f"(f.x), "=f"(f.y) : "l"(v)); return f;
}
__device__ __forceinline__ void ffma2(ull &d, ull a, ull b) {
    asm("fma.rn.f32x2 %0,%1,%2,%0;" : "+l"(d) : "l"(a), "l"(b));
}
__device__ __forceinline__ ull addf2(ull a, ull b) {
    ull r; asm("add.rn.f32x2 %0,%1,%2;" : "=l"(r) : "l"(a), "l"(b)); return r;
}
__device__ __forceinline__ float tanhap(float x) {
    float r; asm("tanh.approx.f32 %0,%1;" : "=f"(r) : "f"(x)); return r;
}
__device__ __forceinline__ float sigap(float x) {
    return fmaf(tanhap(0.5f * x), 0.5f, 0.5f);
}
__device__ __forceinline__ uint32_t tf32rna(float x) {
    uint32_t r; asm("cvt.rna.tf32.f32 %0, %1;" : "=r"(r) : "f"(x)); return r;
}
// mma.sync m16n8k8 tf32: D += A*B (acc in-place)
__device__ __forceinline__ void mma8(float* d, uint32_t a0, uint32_t a1, uint32_t a2, uint32_t a3,
                                     uint32_t b0, uint32_t b1) {
    asm volatile("mma.sync.aligned.m16n8k8.row.col.f32.tf32.tf32.f32 "
        "{%0,%1,%2,%3}, {%4,%5,%6,%7}, {%8,%9}, {%0,%1,%2,%3};"
        : "+f"(d[0]), "+f"(d[1]), "+f"(d[2]), "+f"(d[3])
        : "r"(a0), "r"(a1), "r"(a2), "r"(a3), "r"(b0), "r"(b1));
}

// =====================================================================
// Kernel 0: counting sort rows by seq_len DESC -> g_perm; exclusive
// prefix sum of sorted lengths -> g_coff.
// =====================================================================
__global__ void __launch_bounds__(1024) dien_sort_kernel(const int* __restrict__ seq)
{
    __shared__ int s[1024];
    __shared__ int sperm[1024];
    __shared__ int cnt[256];
    __shared__ int cur[256];
    __shared__ int buf[1024];
    const int tid = threadIdx.x;

    s[tid] = seq[tid];
    if (tid < 256) { cnt[tid] = 0; cur[tid] = 0; }
    __syncthreads();
    atomicAdd(&cnt[s[tid] & 255], 1);
    __syncthreads();
    if (tid < 256) buf[tid] = cnt[tid];
    __syncthreads();
    for (int off = 1; off < 256; off <<= 1) {
        int v = 0;
        if (tid < 256) { v = buf[tid]; if (tid + off < 256) v += buf[tid + off]; }
        __syncthreads();
        if (tid < 256) buf[tid] = v;
        __syncthreads();
    }
    {
        int v = s[tid] & 255;
        int start = buf[v] - cnt[v];
        int rank = atomicAdd(&cur[v], 1);
        sperm[start + rank] = tid;
    }
    __syncthreads();
    g_perm[tid] = sperm[tid];
    int sl = s[sperm[tid]];
    buf[tid] = sl;
    __syncthreads();
    for (int off = 1; off < 1024; off <<= 1) {
        int v = buf[tid] + ((tid >= off) ? buf[tid - off] : 0);
        __syncthreads();
        buf[tid] = v;
        __syncthreads();
    }
    g_coff[tid] = buf[tid] - sl;
    if (tid == 1023) g_coff[1024] = buf[1023];
}

// =====================================================================
// Kernel 0b: pack weight fragments (hi/lo tf32 split).
// =====================================================================
__global__ void __launch_bounds__(256) dien_prep_kernel(
    const float* __restrict__ Wg, const float* __restrict__ Wc)
{
    int idx = blockIdx.x * 256 + threadIdx.x;   // < 24*16*32 = 12288
    if (idx >= 12288) return;
    int l = idx & 31, ks = (idx >> 5) & 15, mt = idx >> 9;
    int tig = l & 3, gid = l >> 2;
    int c0 = mt * 16 + gid, c1 = c0 + 8;
    int k0 = ks * 8 + tig, k1 = k0 + 4;

    float w[4];
    w[0] = (c0 < 256) ? Wg[k0 * 256 + c0] : Wc[k0 * 128 + c0 - 256];
    w[1] = (c1 < 256) ? Wg[k0 * 256 + c1] : Wc[k0 * 128 + c1 - 256];
    w[2] = (c0 < 256) ? Wg[k1 * 256 + c0] : Wc[k1 * 128 + c0 - 256];
    w[3] = (c1 < 256) ? Wg[k1 * 256 + c1] : Wc[k1 * 128 + c1 - 256];

    uint4 hi, lo;
    uint32_t* hp = &hi.x; uint32_t* lp = &lo.x;
    #pragma unroll
    for (int i = 0; i < 4; i++) {
        uint32_t h = tf32rna(w[i]);
        hp[i] = h;
        lp[i] = tf32rna(w[i] - __uint_as_float(h));
    }
    size_t base = ((size_t)(mt * 16 + ks) * 32 + l) * 2;
    g_wpack[base] = hi;
    g_wpack[base + 1] = lo;
}

// =====================================================================
// Phase 1: split-tf32 mma.sync xproj with SMEM-staged coalesced epilogue.
// =====================================================================
__global__ void __launch_bounds__(256, 1) dien_xproj_mma(
    const float* __restrict__ X,
    const float* __restrict__ bg, const float* __restrict__ bc)
{
    extern __shared__ char smraw[];
    float4* Xp4  = (float4*)smraw;                   // [128 row][65] 16B recs = 133120 B
    float* stage = (float*)(smraw + 133120);         // [128 row][132]          = 67584 B
    int* scoff   = (int*)(smraw + 133120 + 67584);   // 1025
    int* srcrow  = scoff + 1025;                     // 128

    const int tid  = threadIdx.x;
    const int lane = tid & 31;
    const int w    = tid >> 5;
    const int r0   = blockIdx.x * 128;

    const int total = g_coff[1024];
    if (r0 >= total) return;

    for (int i = tid; i < 1025; i += 256) scoff[i] = g_coff[i];
    __syncthreads();
    if (tid < 128) {
        int vr = r0 + tid;
        int sr = -1;
        if (vr < total) {
            int lo = 0, hi = 1024;
            while (hi - lo > 1) { int mid = (lo + hi) >> 1; if (scoff[mid] <= vr) lo = mid; else hi = mid; }
            sr = g_perm[lo] * TLEN + (vr - scoff[lo]);
        }
        srcrow[tid] = sr;
    }
    __syncthreads();

    // ---- gather + hi/lo split into fragment-packed layout ----
    {
        const float4* X4 = (const float4*)X;
        float* Xf = (float*)Xp4;
        for (int idx = tid; idx < 4096; idx += 256) {
            int row = idx >> 5, k4 = idx & 31;
            int sr = srcrow[row];
            float4 v = make_float4(0.f, 0.f, 0.f, 0.f);
            if (sr >= 0) v = X4[(size_t)sr * 32 + k4];
            #pragma unroll
            for (int j = 0; j < 4; j++) {
                int k = k4 * 4 + j;
                float x = (j == 0) ? v.x : (j == 1) ? v.y : (j == 2) ? v.z : v.w;
                uint32_t hb = tf32rna(x);
                uint32_t lb = tf32rna(x - __uint_as_float(hb));
                int ks = k >> 3, within = k & 7;
                int tg = within & 3, half = within >> 2;
                int base = (row * 65 + ks * 4 + tg) * 4;
                Xf[base + half]     = __uint_as_float(hb);
                Xf[base + 2 + half] = __uint_as_float(lb);
            }
        }
    }
    __syncthreads();

    const int tig = lane & 3, gid = lane >> 2;

    for (int round = 0; round < 3; round++) {
        const int mt = round * 8 + w;
        const uint4* wp = g_wpack + ((size_t)(mt * 16) * 32 + lane) * 2;

        float acc[16][4];
        #pragma unroll
        for (int nf = 0; nf < 16; nf++)
            #pragma unroll
            for (int i = 0; i < 4; i++) acc[nf][i] = 0.f;

        #pragma unroll 2
        for (int ks = 0; ks < 16; ks++) {
            uint4 ah = wp[(size_t)ks * 64];
            uint4 al = wp[(size_t)ks * 64 + 1];
            #pragma unroll
            for (int nf = 0; nf < 16; nf++) {
                float4 b = Xp4[(nf * 8 + gid) * 65 + ks * 4 + tig];
                uint32_t bh0 = __float_as_uint(b.x), bh1 = __float_as_uint(b.y);
                uint32_t bl0 = __float_as_uint(b.z), bl1 = __float_as_uint(b.w);
                mma8(acc[nf], ah.x, ah.y, ah.z, ah.w, bh0, bh1);
                mma8(acc[nf], ah.x, ah.y, ah.z, ah.w, bl0, bl1);
                mma8(acc[nf], al.x, al.y, al.z, al.w, bh0, bh1);
            }
        }

        // ---- epilogue: stage to smem (conflict-free), then coalesced store ----
        int colg0 = mt * 16 + gid, colg1 = colg0 + 8;   // global cols (for bias)
        int cl0 = w * 16 + gid, cl1 = cl0 + 8;          // local cols in stage
        float bias0 = (colg0 < 256) ? bg[colg0] : bc[colg0 - 256];
        float bias1 = (colg1 < 256) ? bg[colg1] : bc[colg1 - 256];
        #pragma unroll
        for (int nf = 0; nf < 16; nf++) {
            int row0 = nf * 8 + 2 * tig, row1 = row0 + 1;
            stage[row0 * 132 + cl0] = acc[nf][0] + bias0;
            stage[row1 * 132 + cl0] = acc[nf][1] + bias0;
            stage[row0 * 132 + cl1] = acc[nf][2] + bias1;
            stage[row1 * 132 + cl1] = acc[nf][3] + bias1;
        }
        __syncthreads();

        for (int idx = tid; idx < 128 * 32; idx += 256) {
            int row = idx >> 5, c4 = idx & 31;
            int vr = r0 + row;
            if (vr < total) {
                const float* sp = stage + row * 132 + c4 * 4;
                *(float4*)&g_xproj[(size_t)vr * NXC + round * 128 + c4 * 4] =
                    make_float4(sp[0], sp[1], sp[2], sp[3]);
            }
        }
        __syncthreads();   // stage reused next round
    }
}

// =====================================================================
// Phase 2 (R8 structure + tail zero-fill): GRU on sorted 4-row groups.
// 256 CTAs x 512 thr. Replaces the global memset of d_out.
// =====================================================================
__global__ void __launch_bounds__(512, 1) dien_gru_kernel(
    const float* __restrict__ Wg, const float* __restrict__ Wc,
    const int* __restrict__ seqlen, float* __restrict__ out)
{
    extern __shared__ char smraw[];
    float* whc = (float*)smraw;                 // [128 k][128 col]   65536 B
    ull*   hp  = (ull*)(smraw + 65536);         // [2 pair][128 k]     2048 B
    ull*   rhp = hp + 256;                      // [2 pair][128 k]     2048 B
    ull*   red = rhp + 256;                     // 4096 ull           32768 B

    const int tid = threadIdx.x;
    const int jc  = tid & 127;
    const int q   = tid >> 7;            // 0..3, k-split 32
    const int k0  = q * 32;

    for (int i = tid; i < 128 * 128; i += 512) whc[i] = Wc[128 * 128 + i];

    float wgr[32], wgu[32];
    #pragma unroll
    for (int i = 0; i < 32; i++) {
        wgr[i] = Wg[(size_t)(128 + k0 + i) * 256 + jc];
        wgu[i] = Wg[(size_t)(128 + k0 + i) * 256 + jc + 128];
    }

    const int g  = blockIdx.x;
    const int rA0 = g_perm[4 * g];
    const int maxseq = seqlen[rA0];

    const int posA = 4 * g + 2 * (q & 1);
    const int posB = posA + 1;
    const int rowA = g_perm[(q < 2) ? posA : 4 * g];
    const int rowB = g_perm[(q < 2) ? posB : 4 * g];
    const int cofA = g_coff[(q < 2) ? posA : 4 * g];
    const int cofB = g_coff[(q < 2) ? posB : 4 * g];
    const int sqa = seqlen[rowA];
    const int sqb = seqlen[rowB];

    if (tid < 256) hp[tid] = 0ull;
    __syncthreads();

    const float* xa = g_xproj + (size_t)cofA * NXC + jc;
    const float* xb = g_xproj + (size_t)cofB * NXC + jc;
    float* oa = out + (size_t)rowA * TLEN * HDIM + jc;
    float* ob = out + (size_t)rowB * TLEN * HDIM + jc;

    const ulonglong2* h2 = (const ulonglong2*)hp  + (k0 >> 1);
    const ulonglong2* r2 = (const ulonglong2*)rhp + (k0 >> 1);
    const float* wcp = whc + k0 * 128 + jc;

    for (int t = 0; t < maxseq; t++) {
        float xra = 0.f, xrb = 0.f, xua = 0.f, xub = 0.f, xca = 0.f, xcb = 0.f;
        if (q < 2) {
            const float* p0 = xa + (size_t)t * NXC;
            const float* p1 = xb + (size_t)t * NXC;
            if (t < sqa) { xra = p0[0]; xua = p0[128]; xca = p0[256]; }
            if (t < sqb) { xrb = p1[0]; xub = p1[128]; xcb = p1[256]; }
        }

        ull ar0 = 0, ar1 = 0, au0 = 0, au1 = 0;
        #pragma unroll
        for (int i = 0; i < 16; i++) {
            ulonglong2 a0 = h2[i];
            ulonglong2 a1 = h2[64 + i];
            ull w0 = dup2(wgr[2 * i]), w1 = dup2(wgr[2 * i + 1]);
            ull v0 = dup2(wgu[2 * i]), v1 = dup2(wgu[2 * i + 1]);
            ffma2(ar0, a0.x, w0); ffma2(ar0, a0.y, w1);
            ffma2(ar1, a1.x, w0); ffma2(ar1, a1.y, w1);
            ffma2(au0, a0.x, v0); ffma2(au0, a0.y, v1);
            ffma2(au1, a1.x, v0); ffma2(au1, a1.y, v1);
        }
        {
            ull* st = red + q * 1024 + jc;
            st[0]   = ar0; st[128] = ar1;
            st[512] = au0; st[640] = au1;
        }
        __syncthreads();

        float r_a, r_b, u_a, u_b; float2 Ho;
        if (q < 2) {
            const ull* rd = red + q * 128 + jc;
            ull zr = rd[0], zu = rd[512];
            #pragma unroll
            for (int qq = 1; qq < 4; qq++) {
                zr = addf2(zr, rd[qq * 1024]);
                zu = addf2(zu, rd[qq * 1024 + 512]);
            }
            float2 Zr = unpack2(zr), Zu = unpack2(zu);
            r_a = sigap(Zr.x + xra); r_b = sigap(Zr.y + xrb);
            u_a = sigap(Zu.x + xua); u_b = sigap(Zu.y + xub);
            Ho = unpack2(hp[q * 128 + jc]);
            rhp[q * 128 + jc] = pack2(r_a * Ho.x, r_b * Ho.y);
        }
        __syncthreads();

        ull c0 = 0, c1 = 0;
        #pragma unroll
        for (int i = 0; i < 16; i++) {
            ulonglong2 a0 = r2[i];
            ulonglong2 a1 = r2[64 + i];
            ull w0 = dup2(wcp[(2 * i) * 128]);
            ull w1 = dup2(wcp[(2 * i + 1) * 128]);
            ffma2(c0, a0.x, w0); ffma2(c0, a0.y, w1);
            ffma2(c1, a1.x, w0); ffma2(c1, a1.y, w1);
        }
        {
            ull* st = red + q * 256 + jc;
            st[0] = c0; st[128] = c1;
        }
        __syncthreads();

        if (q < 2) {
            const ull* rd = red + q * 128 + jc;
            ull zc = rd[0];
            #pragma unroll
            for (int qq = 1; qq < 4; qq++) zc = addf2(zc, rd[qq * 256]);
            float2 Zc = unpack2(zc);
            float c_a = tanhap(Zc.x + xca);
            float c_b = tanhap(Zc.y + xcb);
            float hna = fmaf(u_a, Ho.x - c_a, c_a);
            float hnb = fmaf(u_b, Ho.y - c_b, c_b);
            bool va = t < sqa, vb = t < sqb;
            hp[q * 128 + jc] = pack2(va ? hna : Ho.x, vb ? hnb : Ho.y);
            if (va) oa[(size_t)t * HDIM] = hna;
            if (vb) ob[(size_t)t * HDIM] = hnb;
        }
        __syncthreads();
    }

    // ---- tail zero-fill: out[row, t>=seq, :] = 0 (replaces global memset) ----
    #pragma unroll
    for (int rr = 0; rr < 4; rr++) {
        int row = g_perm[4 * g + rr];
        int s = seqlen[row];
        float* op = out + (size_t)row * TLEN * HDIM;
        for (int i = s * HDIM + tid; i < TLEN * HDIM; i += 512) op[i] = 0.f;
    }
}

// =====================================================================
extern "C" void kernel_launch(void* const* d_in, const int* in_sizes, int n_in,
                              void* d_out, int out_size)
{
    const float* X   = (const float*)d_in[0];
    const int*   seq = (const int*)  d_in[1];
    const float* Wg  = (const float*)d_in[2];
    const float* bg  = (const float*)d_in[3];
    const float* Wc  = (const float*)d_in[4];
    const float* bc  = (const float*)d_in[5];
    float* out = (float*)d_out;
    (void)in_sizes; (void)n_in; (void)out_size;

    const int SMEM_MMA = 133120 + 67584 + 1025 * 4 + 128 * 4 + 256;  // ~205.8 KB
    const int SMEM2 = 65536 + 2048 + 2048 + 32768;                   // 102400 B
    cudaFuncSetAttribute(dien_xproj_mma, cudaFuncAttributeMaxDynamicSharedMemorySize, SMEM_MMA);
    cudaFuncSetAttribute(dien_gru_kernel, cudaFuncAttributeMaxDynamicSharedMemorySize, SMEM2);

    dien_sort_kernel<<<1, 1024>>>(seq);
    dien_prep_kernel<<<48, 256>>>(Wg, Wc);
    dien_xproj_mma<<<1600, 256, SMEM_MMA>>>(X, bg, bc);
    dien_gru_kernel<<<GROUPS, 512, SMEM2>>>(Wg, Wc, seq, out);
}